// round 6
// baseline (speedup 1.0000x reference)
#include <cuda_runtime.h>
#include <cuda_fp16.h>
#include <mma.h>

#define N_NODES 100000
#define N_EDGES 1600000
#define NUM_G   256
#define D_IN    128
#define D       64
#define BN_EPS  1e-5f

#define SCAN_TILE 1024
#define NSB ((N_NODES + SCAN_TILE - 1) / SCAN_TILE)   // 98 scan blocks

// ---------------- scratch (device globals; no allocation allowed) ----------
__device__ int   g_count[N_NODES];        // in-degree (excl self loop)
__device__ int   g_fill[N_NODES];         // fill cursors for CSR build
__device__ int   g_rowptr[N_NODES + 1];
__device__ int   g_bsum[NSB + 1];         // block sums / offsets for scan
__device__ int   g_csr[N_EDGES];          // src node per in-edge, grouped by dst
__device__ float g_dinv[N_NODES];
__device__ uint2 g_hs[N_NODES * 16];      // (act @ W) * dinv[row], fp16 (4 halfs/uint2)
__device__ uint2 g_acth[N_NODES * 16];    // pre-BN layer output, fp16
__device__ float g_stats[2 * D];          // column sum, sumsq
__device__ float g_s[D];                  // BN scale
__device__ float g_t[D];                  // BN shift
__device__ float g_pool[NUM_G * D];
__device__ int   g_gcnt[NUM_G];

// ---------------- init: zero all per-launch state --------------------------
__global__ void k_init() {
    int stride = gridDim.x * blockDim.x;
    for (int i = blockIdx.x * blockDim.x + threadIdx.x; i < N_NODES; i += stride) {
        g_count[i] = 0;
        g_fill[i]  = 0;
        if (i < NUM_G * D) g_pool[i] = 0.f;
        if (i < NUM_G)     g_gcnt[i] = 0;
        if (i < 2 * D)     g_stats[i] = 0.f;
    }
}

// ---------------- degree histogram + graph-size histogram (fused) -----------
__global__ void k_count(const int* __restrict__ dst,
                        const int* __restrict__ batch) {
    int e = blockIdx.x * blockDim.x + threadIdx.x;
    if (e < N_EDGES) atomicAdd(&g_count[dst[e]], 1);
    if (e < N_NODES) atomicAdd(&g_gcnt[batch[e]], 1);
}

// ---------------- 3-phase multi-block scan -----------------------------------
__global__ void k_scan1() {
    __shared__ int wsum[32];
    int tid = threadIdx.x, lane = tid & 31, wid = tid >> 5;
    int i = blockIdx.x * SCAN_TILE + tid;
    int v = (i < N_NODES) ? g_count[i] : 0;
    int x = v;
    #pragma unroll
    for (int d = 1; d < 32; d <<= 1) {
        int y = __shfl_up_sync(0xffffffffu, x, d);
        if (lane >= d) x += y;
    }
    if (lane == 31) wsum[wid] = x;
    __syncthreads();
    if (wid == 0) {
        int s = wsum[lane];
        #pragma unroll
        for (int d = 1; d < 32; d <<= 1) {
            int y = __shfl_up_sync(0xffffffffu, s, d);
            if (lane >= d) s += y;
        }
        wsum[lane] = s;
    }
    __syncthreads();
    int excl = x - v + (wid > 0 ? wsum[wid - 1] : 0);
    if (i < N_NODES) g_rowptr[i] = excl;
    if (tid == 0) g_bsum[blockIdx.x] = wsum[31];
}

__global__ void k_scan2() {
    __shared__ int wsum[4];
    int tid = threadIdx.x, lane = tid & 31, wid = tid >> 5;  // 128 threads
    int v = (tid < NSB) ? g_bsum[tid] : 0;
    int x = v;
    #pragma unroll
    for (int d = 1; d < 32; d <<= 1) {
        int y = __shfl_up_sync(0xffffffffu, x, d);
        if (lane >= d) x += y;
    }
    if (lane == 31) wsum[wid] = x;
    __syncthreads();
    if (tid == 0) {
        int c = 0;
        #pragma unroll
        for (int w = 0; w < 4; w++) { int t = wsum[w]; wsum[w] = c; c += t; }
    }
    __syncthreads();
    int excl = x - v + wsum[wid];
    if (tid < NSB) g_bsum[tid] = excl;
    if (tid == NSB - 1) g_bsum[NSB] = excl + v;  // total
}

__global__ void k_scan3() {
    int i = blockIdx.x * blockDim.x + threadIdx.x;
    if (i < N_NODES) {
        g_rowptr[i] += g_bsum[i >> 10];
        g_dinv[i] = rsqrtf((float)(g_count[i] + 1));
    }
    if (i == 0) g_rowptr[N_NODES] = g_bsum[NSB];
}

// ---------------- CSR fill ---------------------------------------------------
__global__ void k_fill(const int* __restrict__ src,
                       const int* __restrict__ dst) {
    int e = blockIdx.x * blockDim.x + threadIdx.x;
    if (e < N_EDGES) {
        int d = dst[e];
        int p = g_rowptr[d] + atomicAdd(&g_fill[d], 1);
        g_csr[p] = src[e];
    }
}

// ---------------- GEMM (wmma fp16->fp32): hs = BN?(act) @ W * dinv[row] -----
// 64-row x 64-col tile per block, 256 threads (8 warps).
#define LDH 72   // padded half leading dim
template <int KDIM, bool APPLY_BN>
__global__ void k_gemm(const float* __restrict__ act_in,
                       const float* __restrict__ W) {
    using namespace nvcuda;
    __shared__ __align__(16) __half As[64 * LDH];
    __shared__ __align__(16) __half Ws[64 * LDH];
    __shared__ __align__(16) float  Cs[64 * 64];

    int tid = threadIdx.x;
    int wid = tid >> 5;
    int wr = wid >> 1;      // warp row tile
    int wc = wid & 1;       // warp col half
    int row0 = blockIdx.x * 64;

    wmma::fragment<wmma::accumulator, 16, 16, 16, float> c0, c1;
    wmma::fill_fragment(c0, 0.f);
    wmma::fill_fragment(c1, 0.f);

    for (int kc = 0; kc < KDIM; kc += 64) {
        if (APPLY_BN) {
            // stage from fp16 activations; KDIM == 64, single pass
            for (int idx = tid; idx < 64 * 16; idx += 256) {
                int r = idx >> 4, q = idx & 15;
                int row = row0 + r;
                float4 f = make_float4(0.f, 0.f, 0.f, 0.f);
                if (row < N_NODES) {
                    uint2 hv = g_acth[row * 16 + q];
                    float2 f0 = __half22float2(*(__half2*)&hv.x);
                    float2 f1 = __half22float2(*(__half2*)&hv.y);
                    int c = q * 4;
                    f.x = fmaxf(f0.x * g_s[c]     + g_t[c],     0.f);
                    f.y = fmaxf(f0.y * g_s[c + 1] + g_t[c + 1], 0.f);
                    f.z = fmaxf(f1.x * g_s[c + 2] + g_t[c + 2], 0.f);
                    f.w = fmaxf(f1.y * g_s[c + 3] + g_t[c + 3], 0.f);
                }
                *(__half2*)&As[r * LDH + q * 4]     = __floats2half2_rn(f.x, f.y);
                *(__half2*)&As[r * LDH + q * 4 + 2] = __floats2half2_rn(f.z, f.w);
            }
        } else {
            for (int idx = tid; idx < 64 * 32; idx += 256) {
                int r = idx >> 5, kk = (idx & 31) * 2;
                int row = row0 + r;
                float2 v = make_float2(0.f, 0.f);
                if (row < N_NODES)
                    v = *(const float2*)&act_in[row * KDIM + kc + kk];
                *(__half2*)&As[r * LDH + kk] = __floats2half2_rn(v.x, v.y);
            }
        }
        for (int idx = tid; idx < 64 * 32; idx += 256) {
            int k = idx >> 5, cc = (idx & 31) * 2;
            float2 v = *(const float2*)&W[(kc + k) * D + cc];
            *(__half2*)&Ws[k * LDH + cc] = __floats2half2_rn(v.x, v.y);
        }
        __syncthreads();

        #pragma unroll
        for (int ks = 0; ks < 64; ks += 16) {
            wmma::fragment<wmma::matrix_a, 16, 16, 16, __half, wmma::row_major> a;
            wmma::fragment<wmma::matrix_b, 16, 16, 16, __half, wmma::row_major> b0, b1;
            wmma::load_matrix_sync(a, &As[(wr * 16) * LDH + ks], LDH);
            wmma::load_matrix_sync(b0, &Ws[ks * LDH + wc * 32], LDH);
            wmma::load_matrix_sync(b1, &Ws[ks * LDH + wc * 32 + 16], LDH);
            wmma::mma_sync(c0, a, b0, c0);
            wmma::mma_sync(c1, a, b1, c1);
        }
        __syncthreads();
    }

    wmma::store_matrix_sync(&Cs[(wr * 16) * 64 + wc * 32],      c0, 64, wmma::mem_row_major);
    wmma::store_matrix_sync(&Cs[(wr * 16) * 64 + wc * 32 + 16], c1, 64, wmma::mem_row_major);
    __syncthreads();

    for (int idx = tid; idx < 64 * 16; idx += 256) {
        int r = idx >> 4, q = idx & 15;
        int row = row0 + r;
        if (row < N_NODES) {
            float di = g_dinv[row];
            const float* cr = &Cs[r * 64 + q * 4];
            uint2 pk;
            *(__half2*)&pk.x = __floats2half2_rn(cr[0] * di, cr[1] * di);
            *(__half2*)&pk.y = __floats2half2_rn(cr[2] * di, cr[3] * di);
            g_hs[row * 16 + q] = pk;
        }
    }
}

// ---------------- aggregation: warp per node, 2 edges per warp-LDG -----------
// 16-lane groups; lane sl covers cols sl*4..sl*4+3 (one uint2 = 4 halfs).
__global__ void k_agg() {
    int tid  = threadIdx.x;
    int lane = tid & 31;
    int sub  = lane >> 4;        // edge slot 0/1
    int sl   = lane & 15;        // column slot
    int gw   = (blockIdx.x * blockDim.x + tid) >> 5;
    int nw   = (gridDim.x * blockDim.x) >> 5;

    float st_s[4] = {0.f, 0.f, 0.f, 0.f};
    float st_q[4] = {0.f, 0.f, 0.f, 0.f};

    for (int i = gw; i < N_NODES; i += nw) {
        float a0 = 0.f, a1 = 0.f, a2 = 0.f, a3 = 0.f;
        if (sub == 0) {   // self loop counted once
            uint2 hv = g_hs[i * 16 + sl];
            float2 f0 = __half22float2(*(__half2*)&hv.x);
            float2 f1 = __half22float2(*(__half2*)&hv.y);
            a0 = f0.x; a1 = f0.y; a2 = f1.x; a3 = f1.y;
        }
        int rs = g_rowptr[i], re = g_rowptr[i + 1];
        for (int eb = rs; eb < re; eb += 32) {
            int cnt = min(32, re - eb);
            int myi = (eb + lane < re) ? g_csr[eb + lane] : 0;
            int iters = (cnt + 1) >> 1;
            #pragma unroll 4
            for (int j = 0; j < iters; j++) {
                int e = j * 2 + sub;
                int s = __shfl_sync(0xffffffffu, myi, j * 2 + sub);
                if (e < cnt) {
                    uint2 hv = g_hs[s * 16 + sl];
                    float2 f0 = __half22float2(*(__half2*)&hv.x);
                    float2 f1 = __half22float2(*(__half2*)&hv.y);
                    a0 += f0.x; a1 += f0.y; a2 += f1.x; a3 += f1.y;
                }
            }
        }
        // merge the two 16-lane groups
        a0 += __shfl_xor_sync(0xffffffffu, a0, 16);
        a1 += __shfl_xor_sync(0xffffffffu, a1, 16);
        a2 += __shfl_xor_sync(0xffffffffu, a2, 16);
        a3 += __shfl_xor_sync(0xffffffffu, a3, 16);
        if (sub == 0) {
            float di = g_dinv[i];
            float o0 = a0 * di, o1 = a1 * di, o2 = a2 * di, o3 = a3 * di;
            uint2 pk;
            *(__half2*)&pk.x = __floats2half2_rn(o0, o1);
            *(__half2*)&pk.y = __floats2half2_rn(o2, o3);
            g_acth[i * 16 + sl] = pk;
            st_s[0] += o0; st_s[1] += o1; st_s[2] += o2; st_s[3] += o3;
            st_q[0] += o0 * o0; st_q[1] += o1 * o1; st_q[2] += o2 * o2; st_q[3] += o3 * o3;
        }
    }

    __shared__ float ssum[2 * D];
    if (tid < 2 * D) ssum[tid] = 0.f;
    __syncthreads();
    if (sub == 0) {
        #pragma unroll
        for (int k = 0; k < 4; k++) {
            atomicAdd(&ssum[sl * 4 + k],     st_s[k]);
            atomicAdd(&ssum[D + sl * 4 + k], st_q[k]);
        }
    }
    __syncthreads();
    if (tid < 2 * D) atomicAdd(&g_stats[tid], ssum[tid]);
}

// ---------------- BN scale/shift from stats (also re-zeroes stats) ----------
__global__ void k_st(const float* __restrict__ gamma,
                     const float* __restrict__ beta) {
    int c = threadIdx.x;
    float inv_n = 1.f / (float)N_NODES;
    float mean = g_stats[c] * inv_n;
    float var  = g_stats[D + c] * inv_n - mean * mean;
    float sc = gamma[c] * rsqrtf(var + BN_EPS);
    g_s[c] = sc;
    g_t[c] = beta[c] - mean * sc;
    g_stats[c] = 0.f;
    g_stats[D + c] = 0.f;
}

// ---------------- pooling: segmented accumulation (batch is sorted) ---------
#define POOL_CHUNK 256
__global__ void k_pool(const int* __restrict__ batch) {
    int tid  = threadIdx.x;
    int c    = tid & 63;
    int sub  = tid >> 6;
    int base = blockIdx.x * POOL_CHUNK + sub * 64;
    int end  = min(base + 64, N_NODES);
    float sc = g_s[c], tc = g_t[c];
    const __half* ph = (const __half*)g_acth;
    float acc = 0.f;
    int curg = -1;
    for (int n = base; n < end; n++) {
        int g = batch[n];
        float v = fmaxf(__half2float(ph[n * D + c]) * sc + tc, 0.f);
        if (g != curg) {
            if (curg >= 0) atomicAdd(&g_pool[curg * D + c], acc);
            acc = 0.f; curg = g;
        }
        acc += v;
    }
    if (curg >= 0) atomicAdd(&g_pool[curg * D + c], acc);
}

__global__ void k_final(float* __restrict__ out) {
    int idx = blockIdx.x * blockDim.x + threadIdx.x;
    if (idx < NUM_G * D) {
        int g = idx >> 6;
        out[idx] = g_pool[idx] / fmaxf((float)g_gcnt[g], 1.f);
    }
}

// ---------------- host launch ------------------------------------------------
extern "C" void kernel_launch(void* const* d_in, const int* in_sizes, int n_in,
                              void* d_out, int out_size) {
    const float* x     = (const float*)d_in[0];
    const int*   ei    = (const int*)d_in[1];   // [2, E] int32
    const int*   batch = (const int*)d_in[3];
    const float* W1 = (const float*)d_in[4];
    const float* g1 = (const float*)d_in[6];
    const float* be1 = (const float*)d_in[7];
    const float* W2 = (const float*)d_in[8];
    const float* g2 = (const float*)d_in[10];
    const float* be2 = (const float*)d_in[11];
    const float* W3 = (const float*)d_in[12];
    const float* g3 = (const float*)d_in[14];
    const float* be3 = (const float*)d_in[15];
    float* out = (float*)d_out;

    const int* src = ei;
    const int* dst = ei + N_EDGES;

    const int EB = (N_EDGES + 255) / 256;
    const int NB = (N_NODES + 255) / 256;
    const int GEMM_B = (N_NODES + 63) / 64;

    k_init<<<512, 256>>>();
    k_count<<<EB, 256>>>(dst, batch);
    k_scan1<<<NSB, SCAN_TILE>>>();
    k_scan2<<<1, 128>>>();
    k_scan3<<<NB, 256>>>();
    k_fill<<<EB, 256>>>(src, dst);

    // layer 1
    k_gemm<D_IN, false><<<GEMM_B, 256>>>(x, W1);
    k_agg<<<2048, 256>>>();
    k_st<<<1, 64>>>(g1, be1);

    // layer 2
    k_gemm<D, true><<<GEMM_B, 256>>>(nullptr, W2);
    k_agg<<<2048, 256>>>();
    k_st<<<1, 64>>>(g2, be2);

    // layer 3
    k_gemm<D, true><<<GEMM_B, 256>>>(nullptr, W3);
    k_agg<<<2048, 256>>>();
    k_st<<<1, 64>>>(g3, be3);

    // pool + finalize
    k_pool<<<(N_NODES + POOL_CHUNK - 1) / POOL_CHUNK, 256>>>(batch);
    k_final<<<(NUM_G * D + 255) / 256, 256>>>(out);
}